// round 10
// baseline (speedup 1.0000x reference)
#include <cuda_runtime.h>
#include <cuda_bf16.h>

#define N_NODES 60000
#define D 128
#define IN_RNN 257   // D + 1 + FEAT
#define ALPHA 0.1f

// Scratch (allocation-free rule: __device__ globals; zero-initialized at load)
__device__ float g_support[N_NODES * D];
__device__ float g_agg[N_NODES * D];

// ---------------------------------------------------------------------------
// GEMM: g_support[n, d] = sum_k X[n, k] * W[k, d]
// BM=64, BN=128, BK=32, 256 threads, per-thread tile 8x4.
// FUSED==0: X = external pointer (layer 1). Also zeroes this block's 64-row
//           slice of g_agg (replaces the standalone zero kernel).
// FUSED==1: X[n,k] = relu(ALPHA*g_agg[n,k] + (1-ALPHA)*init[n,k]), and g_agg
//           is re-zeroed in place after being read (each element read once).
// ---------------------------------------------------------------------------
template <int FUSED>
__global__ void __launch_bounds__(256) gemm_t(const float* __restrict__ Xext,
                                              const float* __restrict__ init,
                                              const float* __restrict__ W,
                                              int n_rows) {
    __shared__ float As[64][33];
    __shared__ float Bs[32][128];

    const int block_row = blockIdx.x * 64;
    const int t  = threadIdx.x;
    const int tc = t & 31;
    const int tr = t >> 5;

    float acc[8][4];
    #pragma unroll
    for (int i = 0; i < 8; i++)
        #pragma unroll
        for (int j = 0; j < 4; j++) acc[i][j] = 0.0f;

    for (int k0 = 0; k0 < 128; k0 += 32) {
        #pragma unroll
        for (int i = 0; i < 2; i++) {
            int idx = t + i * 256;
            int r = idx >> 3;
            int c = (idx & 7) * 4;
            int grow = block_row + r;
            float4 v = make_float4(0.f, 0.f, 0.f, 0.f);
            if (grow < n_rows) {
                long off = (long)grow * 128 + k0 + c;
                if (FUSED == 0) {
                    v = *reinterpret_cast<const float4*>(&Xext[off]);
                } else {
                    float4 a = *reinterpret_cast<const float4*>(&g_agg[off]);
                    float4 b = *reinterpret_cast<const float4*>(&init[off]);
                    v.x = fmaxf(ALPHA * a.x + (1.f - ALPHA) * b.x, 0.f);
                    v.y = fmaxf(ALPHA * a.y + (1.f - ALPHA) * b.y, 0.f);
                    v.z = fmaxf(ALPHA * a.z + (1.f - ALPHA) * b.z, 0.f);
                    v.w = fmaxf(ALPHA * a.w + (1.f - ALPHA) * b.w, 0.f);
                    // re-zero agg for the layer-2 scatter
                    *reinterpret_cast<float4*>(&g_agg[off]) =
                        make_float4(0.f, 0.f, 0.f, 0.f);
                }
            }
            As[r][c + 0] = v.x; As[r][c + 1] = v.y;
            As[r][c + 2] = v.z; As[r][c + 3] = v.w;
        }
        #pragma unroll
        for (int i = 0; i < 4; i++) {
            int idx = t + i * 256;
            int r = idx >> 5;
            int c = (idx & 31) * 4;
            float4 v = *reinterpret_cast<const float4*>(&W[(k0 + r) * 128 + c]);
            *reinterpret_cast<float4*>(&Bs[r][c]) = v;
        }
        __syncthreads();

        #pragma unroll
        for (int kk = 0; kk < 32; kk++) {
            float a[8];
            #pragma unroll
            for (int i = 0; i < 8; i++) a[i] = As[tr * 8 + i][kk];
            float4 b = *reinterpret_cast<const float4*>(&Bs[kk][tc * 4]);
            #pragma unroll
            for (int i = 0; i < 8; i++) {
                acc[i][0] = fmaf(a[i], b.x, acc[i][0]);
                acc[i][1] = fmaf(a[i], b.y, acc[i][1]);
                acc[i][2] = fmaf(a[i], b.z, acc[i][2]);
                acc[i][3] = fmaf(a[i], b.w, acc[i][3]);
            }
        }
        __syncthreads();
    }

    #pragma unroll
    for (int i = 0; i < 8; i++) {
        int grow = block_row + tr * 8 + i;
        if (grow < n_rows) {
            float4 v = make_float4(acc[i][0], acc[i][1], acc[i][2], acc[i][3]);
            *reinterpret_cast<float4*>(&g_support[grow * 128 + tc * 4]) = v;
        }
    }

    if (FUSED == 0) {
        // Zero this block's 64-row slice of g_agg (clears previous replay's
        // layer-2 scatter residue before scatter1 runs).
        #pragma unroll
        for (int i = 0; i < 8; i++) {
            int idx = t + i * 256;           // float4 slot within 64x128 slice
            int r = idx >> 5;                // 32 float4 per row
            int c = (idx & 31) * 4;
            int grow = block_row + r;
            if (grow < n_rows)
                *reinterpret_cast<float4*>(&g_agg[(long)grow * 128 + c]) =
                    make_float4(0.f, 0.f, 0.f, 0.f);
        }
    }
}

// ---------------------------------------------------------------------------
// Edge scatter: g_agg[erow[e]] += eval[e] * g_support[ecol[e]]
// One warp per edge; lane handles 4 columns via ONE red.global.add.v4.f32.
// ---------------------------------------------------------------------------
__global__ void scatter_kernel(const int* __restrict__ erow,
                               const int* __restrict__ ecol,
                               const float* __restrict__ eval_,
                               int n_edges) {
    int warp = (blockIdx.x * blockDim.x + threadIdx.x) >> 5;
    int lane = threadIdx.x & 31;
    if (warp >= n_edges) return;
    int col = ecol[warp];            // warp-uniform broadcast loads
    int row = erow[warp];
    float v  = eval_[warp];
    float4 s = *reinterpret_cast<const float4*>(&g_support[col * 128 + lane * 4]);
    float* dst = &g_agg[row * 128 + lane * 4];
    asm volatile("red.global.add.v4.f32 [%0], {%1, %2, %3, %4};"
                 :: "l"(dst), "f"(s.x * v), "f"(s.y * v), "f"(s.z * v), "f"(s.w * v)
                 : "memory");
}

// ---------------------------------------------------------------------------
// Fused layer-2 blend (per gathered row) + RNNCell(tanh) + L2 normalize.
// One block per batch row; thread d computes h[b][d].
// code_embed[d] = relu(ALPHA*agg[cid,d] + (1-ALPHA)*init[cid,d])
// ---------------------------------------------------------------------------
__global__ void rnn_norm_kernel(const float* __restrict__ init,     // [N,128]
                                const float* __restrict__ patient,  // [P,128]
                                const float* __restrict__ td,       // [B,1]
                                const float* __restrict__ feat,     // [B,128]
                                const float* __restrict__ Wih,      // [128,257]
                                const float* __restrict__ bih,      // [128]
                                const float* __restrict__ Whh,      // [128,128]
                                const float* __restrict__ bhh,      // [128]
                                const int* __restrict__ codeid,     // [B]
                                const int* __restrict__ patientid,  // [1]
                                float* __restrict__ out) {          // [B,128]
    __shared__ float s_in[IN_RNN];
    __shared__ float s_ce[D];
    __shared__ float s_red[D];

    const int b = blockIdx.x;
    const int d = threadIdx.x;       // 0..127
    const int pid = patientid[0];

    s_in[d] = patient[pid * 128 + d];
    if (d == 0) s_in[128] = td[b];
    s_in[129 + d] = feat[b * 128 + d];
    const int cid = codeid[b];
    {
        float a = g_agg[(long)cid * 128 + d];
        float i = init[(long)cid * 128 + d];
        s_ce[d] = fmaxf(ALPHA * a + (1.f - ALPHA) * i, 0.f);
    }
    __syncthreads();

    float acc = bih[d] + bhh[d];
    const float* wih = &Wih[d * IN_RNN];
    #pragma unroll 4
    for (int k = 0; k < IN_RNN; k++) acc = fmaf(s_in[k], wih[k], acc);
    const float* whh = &Whh[d * D];
    #pragma unroll 4
    for (int k = 0; k < D; k++) acc = fmaf(s_ce[k], whh[k], acc);

    float h = tanhf(acc);
    s_red[d] = h * h;
    __syncthreads();
    #pragma unroll
    for (int s = 64; s > 0; s >>= 1) {
        if (d < s) s_red[d] += s_red[d + s];
        __syncthreads();
    }
    float nrm = fmaxf(sqrtf(s_red[0]), 1e-12f);
    out[b * 128 + d] = h / nrm;
}

// ---------------------------------------------------------------------------
extern "C" void kernel_launch(void* const* d_in, const int* in_sizes, int n_in,
                              void* d_out, int out_size) {
    const float* code_dynamic = (const float*)d_in[0];
    const float* init_x       = (const float*)d_in[1];
    const float* patient      = (const float*)d_in[2];
    const float* timediffs    = (const float*)d_in[3];
    const float* features     = (const float*)d_in[4];
    const float* edge_val     = (const float*)d_in[5];
    const float* W1           = (const float*)d_in[6];
    const float* W2           = (const float*)d_in[7];
    const float* W_ih         = (const float*)d_in[8];
    const float* b_ih         = (const float*)d_in[9];
    const float* W_hh         = (const float*)d_in[10];
    const float* b_hh         = (const float*)d_in[11];
    const int*   edge_row     = (const int*)d_in[12];
    const int*   edge_col     = (const int*)d_in[13];
    const int*   codeid       = (const int*)d_in[14];
    const int*   patientid    = (const int*)d_in[15];
    float* out = (float*)d_out;

    const int n_nodes = in_sizes[0] / D;         // 60000
    const int n_edges = in_sizes[5];             // 600000
    const int batch   = in_sizes[14];            // 256

    const int gemm_grid  = (n_nodes + 63) / 64;
    const int scat_grid  = (n_edges * 32 + 255) / 256;

    // Layer 1 (also zeroes g_agg slice-by-slice)
    gemm_t<0><<<gemm_grid, 256>>>(code_dynamic, nullptr, W1, n_nodes);
    scatter_kernel<<<scat_grid, 256>>>(edge_row, edge_col, edge_val, n_edges);

    // Layer 2: GEMM fused with blend1 + agg re-zero
    gemm_t<1><<<gemm_grid, 256>>>(nullptr, init_x, W2, n_nodes);
    scatter_kernel<<<scat_grid, 256>>>(edge_row, edge_col, edge_val, n_edges);

    // Fused blend2 (256 rows only) + RNN + normalize
    rnn_norm_kernel<<<batch, 128>>>(init_x, patient, timediffs, features,
                                    W_ih, b_ih, W_hh, b_hh, codeid, patientid, out);
}

// round 13
// speedup vs baseline: 1.1600x; 1.1600x over previous
#include <cuda_runtime.h>
#include <cuda_bf16.h>

#define N_NODES 60000
#define E_MAX   600000
#define D 128
#define IN_RNN 257   // D + 1 + FEAT
#define ALPHA 0.1f
#define SCAN_THREADS 1024

// Scratch (allocation-free rule: __device__ globals)
__device__ float g_support[N_NODES * D];
__device__ float g_x[N_NODES * D];
__device__ int   g_cnt[N_NODES];
__device__ int   g_start[N_NODES + 1];
__device__ int   g_cursor[N_NODES];
__device__ int   g_ecol2[E_MAX];
__device__ float g_eval2[E_MAX];

// ---------------------------------------------------------------------------
// GEMM: g_support[n, d] = sum_k X[n, k] * W[k, d]   (plain, as in R8 @328us)
// BM=64, BN=128, BK=32, 256 threads, per-thread tile 8x4.
// SRC==0: X = external pointer; SRC==1: X = g_x
// ---------------------------------------------------------------------------
template <int SRC>
__global__ void __launch_bounds__(256) gemm_t(const float* __restrict__ Xext,
                                              const float* __restrict__ W,
                                              int n_rows) {
    const float* X = (SRC == 0) ? Xext : g_x;
    __shared__ float As[64][33];
    __shared__ float Bs[32][128];

    const int block_row = blockIdx.x * 64;
    const int t  = threadIdx.x;
    const int tc = t & 31;
    const int tr = t >> 5;

    float acc[8][4];
    #pragma unroll
    for (int i = 0; i < 8; i++)
        #pragma unroll
        for (int j = 0; j < 4; j++) acc[i][j] = 0.0f;

    for (int k0 = 0; k0 < 128; k0 += 32) {
        #pragma unroll
        for (int i = 0; i < 2; i++) {
            int idx = t + i * 256;
            int r = idx >> 3;
            int c = (idx & 7) * 4;
            int grow = block_row + r;
            float4 v = make_float4(0.f, 0.f, 0.f, 0.f);
            if (grow < n_rows)
                v = *reinterpret_cast<const float4*>(&X[(long)grow * 128 + k0 + c]);
            As[r][c + 0] = v.x; As[r][c + 1] = v.y;
            As[r][c + 2] = v.z; As[r][c + 3] = v.w;
        }
        #pragma unroll
        for (int i = 0; i < 4; i++) {
            int idx = t + i * 256;
            int r = idx >> 5;
            int c = (idx & 31) * 4;
            float4 v = *reinterpret_cast<const float4*>(&W[(k0 + r) * 128 + c]);
            *reinterpret_cast<float4*>(&Bs[r][c]) = v;
        }
        __syncthreads();

        #pragma unroll
        for (int kk = 0; kk < 32; kk++) {
            float a[8];
            #pragma unroll
            for (int i = 0; i < 8; i++) a[i] = As[tr * 8 + i][kk];
            float4 b = *reinterpret_cast<const float4*>(&Bs[kk][tc * 4]);
            #pragma unroll
            for (int i = 0; i < 8; i++) {
                acc[i][0] = fmaf(a[i], b.x, acc[i][0]);
                acc[i][1] = fmaf(a[i], b.y, acc[i][1]);
                acc[i][2] = fmaf(a[i], b.z, acc[i][2]);
                acc[i][3] = fmaf(a[i], b.w, acc[i][3]);
            }
        }
        __syncthreads();
    }

    #pragma unroll
    for (int i = 0; i < 8; i++) {
        int grow = block_row + tr * 8 + i;
        if (grow < n_rows) {
            float4 v = make_float4(acc[i][0], acc[i][1], acc[i][2], acc[i][3]);
            *reinterpret_cast<float4*>(&g_support[(long)grow * 128 + tc * 4]) = v;
        }
    }
}

// ---------------------------------------------------------------------------
// CSR build: zero counters -> histogram -> scan -> fill
// ---------------------------------------------------------------------------
__global__ void csr_zero_kernel(int n) {
    int i = blockIdx.x * blockDim.x + threadIdx.x;
    if (i < n) g_cnt[i] = 0;
}

__global__ void csr_hist_kernel(const int* __restrict__ erow, int n_edges) {
    int e = blockIdx.x * blockDim.x + threadIdx.x;
    if (e < n_edges) atomicAdd(&g_cnt[erow[e]], 1);
}

// Single-block exclusive scan over g_cnt -> g_start, g_cursor; g_start[n]=total
__global__ void __launch_bounds__(SCAN_THREADS) csr_scan_kernel(int n) {
    __shared__ int ssum[SCAN_THREADS];
    const int t = threadIdx.x;
    const int chunk = (n + SCAN_THREADS - 1) / SCAN_THREADS;
    const int lo = t * chunk;
    const int hi = min(lo + chunk, n);

    int s = 0;
    for (int i = lo; i < hi; i++) s += g_cnt[i];
    ssum[t] = s;
    __syncthreads();

    // Hillis-Steele inclusive scan
    #pragma unroll
    for (int off = 1; off < SCAN_THREADS; off <<= 1) {
        int v = (t >= off) ? ssum[t - off] : 0;
        __syncthreads();
        ssum[t] += v;
        __syncthreads();
    }

    int run = (t == 0) ? 0 : ssum[t - 1];
    for (int i = lo; i < hi; i++) {
        g_start[i]  = run;
        g_cursor[i] = run;
        run += g_cnt[i];
    }
    if (t == 0) g_start[n] = ssum[SCAN_THREADS - 1];
}

__global__ void csr_fill_kernel(const int* __restrict__ erow,
                                const int* __restrict__ ecol,
                                const float* __restrict__ eval_,
                                int n_edges) {
    int e = blockIdx.x * blockDim.x + threadIdx.x;
    if (e >= n_edges) return;
    int row = erow[e];
    int pos = atomicAdd(&g_cursor[row], 1);
    g_ecol2[pos] = ecol[e];
    g_eval2[pos] = eval_[e];
}

// ---------------------------------------------------------------------------
// Pull aggregation + blend + ReLU, all in registers:
//   g_x[row] = relu(ALPHA * sum_i val_i * g_support[col_i] + (1-ALPHA) * init[row])
// One warp per node; lane owns 4 columns. No atomics, no agg buffer.
// ---------------------------------------------------------------------------
__global__ void pull_kernel(const float* __restrict__ init, int n_nodes) {
    int warp = (blockIdx.x * blockDim.x + threadIdx.x) >> 5;
    int lane = threadIdx.x & 31;
    if (warp >= n_nodes) return;

    int s = g_start[warp];
    int e = g_start[warp + 1];

    float ax = 0.f, ay = 0.f, az = 0.f, aw = 0.f;
    for (int i = s; i < e; i++) {
        int col = g_ecol2[i];        // lane-uniform -> broadcast
        float v = g_eval2[i];
        float4 sv = *reinterpret_cast<const float4*>(
            &g_support[(long)col * 128 + lane * 4]);
        ax = fmaf(v, sv.x, ax);
        ay = fmaf(v, sv.y, ay);
        az = fmaf(v, sv.z, az);
        aw = fmaf(v, sv.w, aw);
    }

    float4 b = *reinterpret_cast<const float4*>(&init[(long)warp * 128 + lane * 4]);
    float4 r;
    r.x = fmaxf(ALPHA * ax + (1.f - ALPHA) * b.x, 0.f);
    r.y = fmaxf(ALPHA * ay + (1.f - ALPHA) * b.y, 0.f);
    r.z = fmaxf(ALPHA * az + (1.f - ALPHA) * b.z, 0.f);
    r.w = fmaxf(ALPHA * aw + (1.f - ALPHA) * b.w, 0.f);
    *reinterpret_cast<float4*>(&g_x[(long)warp * 128 + lane * 4]) = r;
}

// ---------------------------------------------------------------------------
// RNNCell(tanh) + L2 normalize. One block per batch row; g_x already blended.
// ---------------------------------------------------------------------------
__global__ void rnn_norm_kernel(const float* __restrict__ patient,  // [P,128]
                                const float* __restrict__ td,       // [B,1]
                                const float* __restrict__ feat,     // [B,128]
                                const float* __restrict__ Wih,      // [128,257]
                                const float* __restrict__ bih,      // [128]
                                const float* __restrict__ Whh,      // [128,128]
                                const float* __restrict__ bhh,      // [128]
                                const int* __restrict__ codeid,     // [B]
                                const int* __restrict__ patientid,  // [1]
                                float* __restrict__ out) {          // [B,128]
    __shared__ float s_in[IN_RNN];
    __shared__ float s_ce[D];
    __shared__ float s_red[D];

    const int b = blockIdx.x;
    const int d = threadIdx.x;       // 0..127
    const int pid = patientid[0];

    s_in[d] = patient[pid * 128 + d];
    if (d == 0) s_in[128] = td[b];
    s_in[129 + d] = feat[b * 128 + d];
    const int cid = codeid[b];
    s_ce[d] = g_x[(long)cid * 128 + d];
    __syncthreads();

    float acc = bih[d] + bhh[d];
    const float* wih = &Wih[d * IN_RNN];
    #pragma unroll 4
    for (int k = 0; k < IN_RNN; k++) acc = fmaf(s_in[k], wih[k], acc);
    const float* whh = &Whh[d * D];
    #pragma unroll 4
    for (int k = 0; k < D; k++) acc = fmaf(s_ce[k], whh[k], acc);

    float h = tanhf(acc);
    s_red[d] = h * h;
    __syncthreads();
    #pragma unroll
    for (int s = 64; s > 0; s >>= 1) {
        if (d < s) s_red[d] += s_red[d + s];
        __syncthreads();
    }
    float nrm = fmaxf(sqrtf(s_red[0]), 1e-12f);
    out[b * 128 + d] = h / nrm;
}

// ---------------------------------------------------------------------------
extern "C" void kernel_launch(void* const* d_in, const int* in_sizes, int n_in,
                              void* d_out, int out_size) {
    const float* code_dynamic = (const float*)d_in[0];
    const float* init_x       = (const float*)d_in[1];
    const float* patient      = (const float*)d_in[2];
    const float* timediffs    = (const float*)d_in[3];
    const float* features     = (const float*)d_in[4];
    const float* edge_val     = (const float*)d_in[5];
    const float* W1           = (const float*)d_in[6];
    const float* W2           = (const float*)d_in[7];
    const float* W_ih         = (const float*)d_in[8];
    const float* b_ih         = (const float*)d_in[9];
    const float* W_hh         = (const float*)d_in[10];
    const float* b_hh         = (const float*)d_in[11];
    const int*   edge_row     = (const int*)d_in[12];
    const int*   edge_col     = (const int*)d_in[13];
    const int*   codeid       = (const int*)d_in[14];
    const int*   patientid    = (const int*)d_in[15];
    float* out = (float*)d_out;

    const int n_nodes = in_sizes[0] / D;         // 60000
    const int n_edges = in_sizes[5];             // 600000
    const int batch   = in_sizes[14];            // 256

    const int gemm_grid = (n_nodes + 63) / 64;
    const int node_grid = (n_nodes + 255) / 256;
    const int edge_grid = (n_edges + 255) / 256;
    const int pull_grid = (n_nodes * 32 + 255) / 256;

    // CSR build (once per launch; edges shared by both layers)
    csr_zero_kernel<<<node_grid, 256>>>(n_nodes);
    csr_hist_kernel<<<edge_grid, 256>>>(edge_row, n_edges);
    csr_scan_kernel<<<1, SCAN_THREADS>>>(n_nodes);
    csr_fill_kernel<<<edge_grid, 256>>>(edge_row, edge_col, edge_val, n_edges);

    // Layer 1
    gemm_t<0><<<gemm_grid, 256>>>(code_dynamic, W1, n_nodes);
    pull_kernel<<<pull_grid, 256>>>(init_x, n_nodes);

    // Layer 2
    gemm_t<1><<<gemm_grid, 256>>>(nullptr, W2, n_nodes);
    pull_kernel<<<pull_grid, 256>>>(init_x, n_nodes);

    // RNN + normalize (g_x rows already blended+ReLU'd)
    rnn_norm_kernel<<<batch, 128>>>(patient, timediffs, features,
                                    W_ih, b_ih, W_hh, b_hh, codeid, patientid, out);
}

// round 14
// speedup vs baseline: 1.2378x; 1.0671x over previous
#include <cuda_runtime.h>
#include <cuda_bf16.h>
#include <mma.h>

using namespace nvcuda;

#define N_NODES 60000
#define E_MAX   600000
#define D 128
#define IN_RNN 257   // D + 1 + FEAT
#define ALPHA 0.1f
#define SCAN_THREADS 1024

// Scratch (allocation-free rule: __device__ globals)
// g_support padded by 64 rows: wmma stores in the last row-block write full
// 16x16 tiles; loads are guarded, stores spill into the slack region.
__device__ float g_support[(N_NODES + 64) * D];
__device__ float g_x[N_NODES * D];
__device__ int   g_cnt[N_NODES];
__device__ int   g_start[N_NODES + 1];
__device__ int   g_cursor[N_NODES];
__device__ int   g_ecol2[E_MAX];
__device__ float g_eval2[E_MAX];

// ---------------------------------------------------------------------------
// tf32 tensor-core GEMM: g_support[n, d] = sum_k X[n, k] * W[k, d]
// BM=64, BN=128, BK=32; 256 threads = 8 warps; warp owns a 16x64 strip.
// SRC==0: X = external pointer; SRC==1: X = g_x
// ---------------------------------------------------------------------------
template <int SRC>
__global__ void __launch_bounds__(256) gemm_tf32(const float* __restrict__ Xext,
                                                 const float* __restrict__ W,
                                                 int n_rows) {
    const float* X = (SRC == 0) ? Xext : g_x;
    __shared__ float As[64][36];    // 64 rows x 32 k (+4 pad, 16B-aligned rows)
    __shared__ float Bs[32][132];   // 32 k x 128 cols (+4 pad)

    const int t = threadIdx.x;
    const int warp = t >> 5;
    const int block_row = blockIdx.x * 64;
    const int rt = warp >> 1;              // row tile 0..3 (16 rows each)
    const int cg = (warp & 1) * 64;        // col group base (0 or 64)

    wmma::fragment<wmma::accumulator, 16, 16, 8, float> c[4];
    #pragma unroll
    for (int i = 0; i < 4; i++) wmma::fill_fragment(c[i], 0.0f);

    for (int k0 = 0; k0 < 128; k0 += 32) {
        // A tile: 64x32 = 512 float4, 2 per thread
        #pragma unroll
        for (int i = 0; i < 2; i++) {
            int idx = t + i * 256;
            int r = idx >> 3;
            int cc = (idx & 7) * 4;
            int grow = block_row + r;
            float4 v = make_float4(0.f, 0.f, 0.f, 0.f);
            if (grow < n_rows)
                v = *reinterpret_cast<const float4*>(&X[(long)grow * 128 + k0 + cc]);
            *reinterpret_cast<float4*>(&As[r][cc]) = v;
        }
        // B tile: 32x128 = 1024 float4, 4 per thread
        #pragma unroll
        for (int i = 0; i < 4; i++) {
            int idx = t + i * 256;
            int r = idx >> 5;
            int cc = (idx & 31) * 4;
            float4 v = *reinterpret_cast<const float4*>(&W[(long)(k0 + r) * 128 + cc]);
            *reinterpret_cast<float4*>(&Bs[r][cc]) = v;
        }
        __syncthreads();

        #pragma unroll
        for (int kk = 0; kk < 32; kk += 8) {
            wmma::fragment<wmma::matrix_a, 16, 16, 8, wmma::precision::tf32,
                           wmma::row_major> a;
            wmma::load_matrix_sync(a, &As[rt * 16][kk], 36);
            #pragma unroll
            for (int i = 0; i < a.num_elements; i++)
                a.x[i] = wmma::__float_to_tf32(a.x[i]);
            #pragma unroll
            for (int ct = 0; ct < 4; ct++) {
                wmma::fragment<wmma::matrix_b, 16, 16, 8, wmma::precision::tf32,
                               wmma::row_major> b;
                wmma::load_matrix_sync(b, &Bs[kk][cg + ct * 16], 132);
                #pragma unroll
                for (int i = 0; i < b.num_elements; i++)
                    b.x[i] = wmma::__float_to_tf32(b.x[i]);
                wmma::mma_sync(c[ct], a, b, c[ct]);
            }
        }
        __syncthreads();
    }

    #pragma unroll
    for (int ct = 0; ct < 4; ct++) {
        wmma::store_matrix_sync(
            &g_support[(long)(block_row + rt * 16) * 128 + cg + ct * 16],
            c[ct], 128, wmma::mem_row_major);
    }
}

// ---------------------------------------------------------------------------
// CSR build: zero counters -> histogram -> scan -> fill
// ---------------------------------------------------------------------------
__global__ void csr_zero_kernel(int n) {
    int i = blockIdx.x * blockDim.x + threadIdx.x;
    if (i < n) g_cnt[i] = 0;
}

__global__ void csr_hist_kernel(const int* __restrict__ erow, int n_edges) {
    int e = blockIdx.x * blockDim.x + threadIdx.x;
    if (e < n_edges) atomicAdd(&g_cnt[erow[e]], 1);
}

// Single-block exclusive scan over g_cnt -> g_start, g_cursor; g_start[n]=total
__global__ void __launch_bounds__(SCAN_THREADS) csr_scan_kernel(int n) {
    __shared__ int ssum[SCAN_THREADS];
    const int t = threadIdx.x;
    const int chunk = (n + SCAN_THREADS - 1) / SCAN_THREADS;
    const int lo = t * chunk;
    const int hi = min(lo + chunk, n);

    int s = 0;
    for (int i = lo; i < hi; i++) s += g_cnt[i];
    ssum[t] = s;
    __syncthreads();

    #pragma unroll
    for (int off = 1; off < SCAN_THREADS; off <<= 1) {
        int v = (t >= off) ? ssum[t - off] : 0;
        __syncthreads();
        ssum[t] += v;
        __syncthreads();
    }

    int run = (t == 0) ? 0 : ssum[t - 1];
    for (int i = lo; i < hi; i++) {
        g_start[i]  = run;
        g_cursor[i] = run;
        run += g_cnt[i];
    }
    if (t == 0) g_start[n] = ssum[SCAN_THREADS - 1];
}

__global__ void csr_fill_kernel(const int* __restrict__ erow,
                                const int* __restrict__ ecol,
                                const float* __restrict__ eval_,
                                int n_edges) {
    int e = blockIdx.x * blockDim.x + threadIdx.x;
    if (e >= n_edges) return;
    int row = erow[e];
    int pos = atomicAdd(&g_cursor[row], 1);
    g_ecol2[pos] = ecol[e];
    g_eval2[pos] = eval_[e];
}

// ---------------------------------------------------------------------------
// Pull aggregation + blend + ReLU, all in registers:
//   g_x[row] = relu(ALPHA * sum_i val_i * g_support[col_i] + (1-ALPHA) * init[row])
// One warp per node; lane owns 4 columns. No atomics, no agg buffer.
// ---------------------------------------------------------------------------
__global__ void pull_kernel(const float* __restrict__ init, int n_nodes) {
    int warp = (blockIdx.x * blockDim.x + threadIdx.x) >> 5;
    int lane = threadIdx.x & 31;
    if (warp >= n_nodes) return;

    int s = g_start[warp];
    int e = g_start[warp + 1];

    float ax = 0.f, ay = 0.f, az = 0.f, aw = 0.f;
    for (int i = s; i < e; i++) {
        int col = g_ecol2[i];        // lane-uniform -> broadcast
        float v = g_eval2[i];
        float4 sv = *reinterpret_cast<const float4*>(
            &g_support[(long)col * 128 + lane * 4]);
        ax = fmaf(v, sv.x, ax);
        ay = fmaf(v, sv.y, ay);
        az = fmaf(v, sv.z, az);
        aw = fmaf(v, sv.w, aw);
    }

    float4 b = *reinterpret_cast<const float4*>(&init[(long)warp * 128 + lane * 4]);
    float4 r;
    r.x = fmaxf(ALPHA * ax + (1.f - ALPHA) * b.x, 0.f);
    r.y = fmaxf(ALPHA * ay + (1.f - ALPHA) * b.y, 0.f);
    r.z = fmaxf(ALPHA * az + (1.f - ALPHA) * b.z, 0.f);
    r.w = fmaxf(ALPHA * aw + (1.f - ALPHA) * b.w, 0.f);
    *reinterpret_cast<float4*>(&g_x[(long)warp * 128 + lane * 4]) = r;
}

// ---------------------------------------------------------------------------
// RNNCell(tanh) + L2 normalize. One block per batch row; g_x already blended.
// ---------------------------------------------------------------------------
__global__ void rnn_norm_kernel(const float* __restrict__ patient,  // [P,128]
                                const float* __restrict__ td,       // [B,1]
                                const float* __restrict__ feat,     // [B,128]
                                const float* __restrict__ Wih,      // [128,257]
                                const float* __restrict__ bih,      // [128]
                                const float* __restrict__ Whh,      // [128,128]
                                const float* __restrict__ bhh,      // [128]
                                const int* __restrict__ codeid,     // [B]
                                const int* __restrict__ patientid,  // [1]
                                float* __restrict__ out) {          // [B,128]
    __shared__ float s_in[IN_RNN];
    __shared__ float s_ce[D];
    __shared__ float s_red[D];

    const int b = blockIdx.x;
    const int d = threadIdx.x;       // 0..127
    const int pid = patientid[0];

    s_in[d] = patient[pid * 128 + d];
    if (d == 0) s_in[128] = td[b];
    s_in[129 + d] = feat[b * 128 + d];
    const int cid = codeid[b];
    s_ce[d] = g_x[(long)cid * 128 + d];
    __syncthreads();

    float acc = bih[d] + bhh[d];
    const float* wih = &Wih[d * IN_RNN];
    #pragma unroll 4
    for (int k = 0; k < IN_RNN; k++) acc = fmaf(s_in[k], wih[k], acc);
    const float* whh = &Whh[d * D];
    #pragma unroll 4
    for (int k = 0; k < D; k++) acc = fmaf(s_ce[k], whh[k], acc);

    float h = tanhf(acc);
    s_red[d] = h * h;
    __syncthreads();
    #pragma unroll
    for (int s = 64; s > 0; s >>= 1) {
        if (d < s) s_red[d] += s_red[d + s];
        __syncthreads();
    }
    float nrm = fmaxf(sqrtf(s_red[0]), 1e-12f);
    out[b * 128 + d] = h / nrm;
}

// ---------------------------------------------------------------------------
extern "C" void kernel_launch(void* const* d_in, const int* in_sizes, int n_in,
                              void* d_out, int out_size) {
    const float* code_dynamic = (const float*)d_in[0];
    const float* init_x       = (const float*)d_in[1];
    const float* patient      = (const float*)d_in[2];
    const float* timediffs    = (const float*)d_in[3];
    const float* features     = (const float*)d_in[4];
    const float* edge_val     = (const float*)d_in[5];
    const float* W1           = (const float*)d_in[6];
    const float* W2           = (const float*)d_in[7];
    const float* W_ih         = (const float*)d_in[8];
    const float* b_ih         = (const float*)d_in[9];
    const float* W_hh         = (const float*)d_in[10];
    const float* b_hh         = (const float*)d_in[11];
    const int*   edge_row     = (const int*)d_in[12];
    const int*   edge_col     = (const int*)d_in[13];
    const int*   codeid       = (const int*)d_in[14];
    const int*   patientid    = (const int*)d_in[15];
    float* out = (float*)d_out;

    const int n_nodes = in_sizes[0] / D;         // 60000
    const int n_edges = in_sizes[5];             // 600000
    const int batch   = in_sizes[14];            // 256

    const int gemm_grid = (n_nodes + 63) / 64;
    const int node_grid = (n_nodes + 255) / 256;
    const int edge_grid = (n_edges + 255) / 256;
    const int pull_grid = (n_nodes * 32 + 255) / 256;

    // CSR build (once per launch; edges shared by both layers)
    csr_zero_kernel<<<node_grid, 256>>>(n_nodes);
    csr_hist_kernel<<<edge_grid, 256>>>(edge_row, n_edges);
    csr_scan_kernel<<<1, SCAN_THREADS>>>(n_nodes);
    csr_fill_kernel<<<edge_grid, 256>>>(edge_row, edge_col, edge_val, n_edges);

    // Layer 1
    gemm_tf32<0><<<gemm_grid, 256>>>(code_dynamic, W1, n_nodes);
    pull_kernel<<<pull_grid, 256>>>(init_x, n_nodes);

    // Layer 2
    gemm_tf32<1><<<gemm_grid, 256>>>(nullptr, W2, n_nodes);
    pull_kernel<<<pull_grid, 256>>>(init_x, n_nodes);

    // RNN + normalize (g_x rows already blended+ReLU'd)
    rnn_norm_kernel<<<batch, 128>>>(patient, timediffs, features,
                                    W_ih, b_ih, W_hh, b_hh, codeid, patientid, out);
}

// round 17
// speedup vs baseline: 1.7322x; 1.3994x over previous
#include <cuda_runtime.h>
#include <cuda_fp16.h>
#include <mma.h>

using namespace nvcuda;

#define N_NODES 60000
#define E_MAX   600000
#define D 128
#define IN_RNN 257   // D + 1 + FEAT
#define ALPHA 0.1f
#define SCAN_THREADS 1024

// Scratch (allocation-free rule: __device__ globals; referenced ONLY inside
// kernels — never passed as launch arguments from host code).
__device__ __align__(16) __half g_support[(N_NODES + 32) * D];
__device__ __align__(16) __half g_x[N_NODES * D];
__device__ __align__(16) __half g_W1h[D * D];
__device__ __align__(16) __half g_W2h[D * D];
__device__ int   g_cnt[N_NODES];
__device__ int   g_start[N_NODES + 1];
__device__ int   g_cursor[N_NODES];
__device__ __align__(16) int2 g_edge2[E_MAX];   // {col, float_as_int(val)}

// ---------------------------------------------------------------------------
// One-shot W conversion to fp16
// ---------------------------------------------------------------------------
__global__ void convert_w_kernel(const float* __restrict__ W1,
                                 const float* __restrict__ W2) {
    int i = blockIdx.x * blockDim.x + threadIdx.x;
    if (i < D * D) {
        g_W1h[i] = __float2half_rn(W1[i]);
        g_W2h[i] = __float2half_rn(W2[i]);
    }
}

// ---------------------------------------------------------------------------
// fp16 tensor-core GEMM, full K in smem:
//   g_support[n, d] = (half) sum_k X[n, k] * W[k, d]
// BM=32 rows/block, 256 threads = 8 warps; warp owns 16 rows x 32 cols.
// One smem fill + one mma pass (8 k-steps), fp32 accum, staged half epilogue.
// LAYER==1: X = external fp32 pointer, W = g_W1h
// LAYER==2: X = g_x (half),            W = g_W2h
// ---------------------------------------------------------------------------
template <int LAYER>
__global__ void __launch_bounds__(256) gemm_half(const float* __restrict__ Xf,
                                                 int n_rows) {
    const __half* Wh = (LAYER == 1) ? g_W1h : g_W2h;
    __shared__ __half As[32][136];    // 32 rows x 128 k (+8 pad)
    __shared__ __half Bs[128][136];   // 128 k x 128 cols
    float* stage = reinterpret_cast<float*>(&Bs[0][0]);  // reused after mma

    const int t = threadIdx.x;
    const int warp = t >> 5;
    const int block_row = blockIdx.x * 32;
    const int rt = warp >> 2;              // row tile 0..1
    const int cg = (warp & 3) * 32;        // col base 0/32/64/96

    // Load B (full W, 16384 halves = 2048 uint4): 8 per thread
    #pragma unroll
    for (int i = 0; i < 8; i++) {
        int idx = t + i * 256;
        int r = idx >> 4;                  // 16 uint4 per row
        int c = (idx & 15) * 8;
        *reinterpret_cast<uint4*>(&Bs[r][c]) =
            *reinterpret_cast<const uint4*>(&Wh[r * 128 + c]);
    }
    // Load A tile (32 x 128)
    if (LAYER == 1) {
        #pragma unroll
        for (int i = 0; i < 4; i++) {      // 1024 float4, 4 per thread
            int idx = t + i * 256;
            int r = idx >> 5;              // 32 float4 per row
            int c = (idx & 31) * 4;
            int grow = block_row + r;
            float4 v = make_float4(0.f, 0.f, 0.f, 0.f);
            if (grow < n_rows)
                v = *reinterpret_cast<const float4*>(&Xf[(long)grow * 128 + c]);
            *reinterpret_cast<__half2*>(&As[r][c])     = __floats2half2_rn(v.x, v.y);
            *reinterpret_cast<__half2*>(&As[r][c + 2]) = __floats2half2_rn(v.z, v.w);
        }
    } else {
        #pragma unroll
        for (int i = 0; i < 2; i++) {      // 512 uint4 (8 halves), 2 per thread
            int idx = t + i * 256;
            int r = idx >> 4;
            int c = (idx & 15) * 8;
            int grow = block_row + r;
            uint4 v = make_uint4(0u, 0u, 0u, 0u);
            if (grow < n_rows)
                v = *reinterpret_cast<const uint4*>(&g_x[(long)grow * 128 + c]);
            *reinterpret_cast<uint4*>(&As[r][c]) = v;
        }
    }
    __syncthreads();

    wmma::fragment<wmma::accumulator, 16, 16, 16, float> c0, c1;
    wmma::fill_fragment(c0, 0.0f);
    wmma::fill_fragment(c1, 0.0f);

    #pragma unroll
    for (int kk = 0; kk < 128; kk += 16) {
        wmma::fragment<wmma::matrix_a, 16, 16, 16, __half, wmma::row_major> a;
        wmma::load_matrix_sync(a, &As[rt * 16][kk], 136);
        wmma::fragment<wmma::matrix_b, 16, 16, 16, __half, wmma::row_major> b;
        wmma::load_matrix_sync(b, &Bs[kk][cg], 136);
        wmma::mma_sync(c0, a, b, c0);
        wmma::load_matrix_sync(b, &Bs[kk][cg + 16], 136);
        wmma::mma_sync(c1, a, b, c1);
    }
    __syncthreads();   // all mma B-reads done; safe to reuse Bs as staging

    wmma::store_matrix_sync(&stage[(rt * 16) * 128 + cg],      c0, 128,
                            wmma::mem_row_major);
    wmma::store_matrix_sync(&stage[(rt * 16) * 128 + cg + 16], c1, 128,
                            wmma::mem_row_major);
    __syncthreads();

    // Convert stage (32x128 fp32) -> g_support half (padded rows: unguarded ok)
    #pragma unroll
    for (int i = 0; i < 4; i++) {
        int idx = t + i * 256;
        int r = idx >> 5;
        int c = (idx & 31) * 4;
        float4 v = *reinterpret_cast<const float4*>(&stage[r * 128 + c]);
        long grow = block_row + r;
        *reinterpret_cast<__half2*>(&g_support[grow * 128 + c])     = __floats2half2_rn(v.x, v.y);
        *reinterpret_cast<__half2*>(&g_support[grow * 128 + c + 2]) = __floats2half2_rn(v.z, v.w);
    }
}

// ---------------------------------------------------------------------------
// CSR build: zero counters -> histogram -> scan -> fill
// ---------------------------------------------------------------------------
__global__ void csr_zero_kernel(int n) {
    int i = blockIdx.x * blockDim.x + threadIdx.x;
    if (i < n) g_cnt[i] = 0;
}

__global__ void csr_hist_kernel(const int* __restrict__ erow, int n_edges) {
    int e = blockIdx.x * blockDim.x + threadIdx.x;
    if (e < n_edges) atomicAdd(&g_cnt[erow[e]], 1);
}

__global__ void __launch_bounds__(SCAN_THREADS) csr_scan_kernel(int n) {
    __shared__ int ssum[SCAN_THREADS];
    const int t = threadIdx.x;
    const int chunk = (n + SCAN_THREADS - 1) / SCAN_THREADS;
    const int lo = t * chunk;
    const int hi = min(lo + chunk, n);

    int s = 0;
    for (int i = lo; i < hi; i++) s += g_cnt[i];
    ssum[t] = s;
    __syncthreads();

    #pragma unroll
    for (int off = 1; off < SCAN_THREADS; off <<= 1) {
        int v = (t >= off) ? ssum[t - off] : 0;
        __syncthreads();
        ssum[t] += v;
        __syncthreads();
    }

    int run = (t == 0) ? 0 : ssum[t - 1];
    for (int i = lo; i < hi; i++) {
        g_start[i]  = run;
        g_cursor[i] = run;
        run += g_cnt[i];
    }
    if (t == 0) g_start[n] = ssum[SCAN_THREADS - 1];
}

__global__ void csr_fill_kernel(const int* __restrict__ erow,
                                const int* __restrict__ ecol,
                                const float* __restrict__ eval_,
                                int n_edges) {
    int e = blockIdx.x * blockDim.x + threadIdx.x;
    if (e >= n_edges) return;
    int row = erow[e];
    int pos = atomicAdd(&g_cursor[row], 1);
    g_edge2[pos] = make_int2(ecol[e], __float_as_int(eval_[e]));
}

// ---------------------------------------------------------------------------
// Layer-1 pull: aggregation + blend + ReLU (fp32 accum, half gather/output):
//   g_x[row] = (half) relu(ALPHA * sum_i val_i * support[col_i] + (1-ALPHA)*init[row])
// One warp per node; lane owns 4 columns (uint2 = 4 halves). Unroll x4.
// ---------------------------------------------------------------------------
__device__ __forceinline__ void pull_acc(int2 m, uint2 r,
                                         float& ax, float& ay, float& az, float& aw) {
    float v = __int_as_float(m.y);
    float2 f0 = __half22float2(*reinterpret_cast<__half2*>(&r.x));
    float2 f1 = __half22float2(*reinterpret_cast<__half2*>(&r.y));
    ax = fmaf(v, f0.x, ax);
    ay = fmaf(v, f0.y, ay);
    az = fmaf(v, f1.x, az);
    aw = fmaf(v, f1.y, aw);
}

__global__ void pull_kernel(const float* __restrict__ init, int n_nodes) {
    int node = (blockIdx.x * blockDim.x + threadIdx.x) >> 5;
    int lane = threadIdx.x & 31;
    if (node >= n_nodes) return;

    int s = g_start[node];
    int e = g_start[node + 1];

    float ax = 0.f, ay = 0.f, az = 0.f, aw = 0.f;
    int i = s;
    for (; i + 4 <= e; i += 4) {
        int2 m0 = g_edge2[i],     m1 = g_edge2[i + 1];
        int2 m2 = g_edge2[i + 2], m3 = g_edge2[i + 3];
        uint2 r0 = *reinterpret_cast<const uint2*>(&g_support[(long)m0.x * 128 + lane * 4]);
        uint2 r1 = *reinterpret_cast<const uint2*>(&g_support[(long)m1.x * 128 + lane * 4]);
        uint2 r2 = *reinterpret_cast<const uint2*>(&g_support[(long)m2.x * 128 + lane * 4]);
        uint2 r3 = *reinterpret_cast<const uint2*>(&g_support[(long)m3.x * 128 + lane * 4]);
        pull_acc(m0, r0, ax, ay, az, aw);
        pull_acc(m1, r1, ax, ay, az, aw);
        pull_acc(m2, r2, ax, ay, az, aw);
        pull_acc(m3, r3, ax, ay, az, aw);
    }
    for (; i < e; i++) {
        int2 m = g_edge2[i];
        uint2 r = *reinterpret_cast<const uint2*>(&g_support[(long)m.x * 128 + lane * 4]);
        pull_acc(m, r, ax, ay, az, aw);
    }

    float4 b = *reinterpret_cast<const float4*>(&init[(long)node * 128 + lane * 4]);
    float rx = fmaxf(ALPHA * ax + (1.f - ALPHA) * b.x, 0.f);
    float ry = fmaxf(ALPHA * ay + (1.f - ALPHA) * b.y, 0.f);
    float rz = fmaxf(ALPHA * az + (1.f - ALPHA) * b.z, 0.f);
    float rw = fmaxf(ALPHA * aw + (1.f - ALPHA) * b.w, 0.f);
    __half* dst = &g_x[(long)node * 128 + lane * 4];
    *reinterpret_cast<__half2*>(dst)     = __floats2half2_rn(rx, ry);
    *reinterpret_cast<__half2*>(dst + 2) = __floats2half2_rn(rz, rw);
}

// ---------------------------------------------------------------------------
// Fused layer-2 aggregation+blend (fp32, per gathered row) + RNNCell + L2 norm.
// One block per batch row; thread d computes h[b][d]. The 256 needed rows of
// layer-2's output are computed here directly from g_support (half) + CSR —
// the full-graph layer-2 pull is never materialized.
// ---------------------------------------------------------------------------
__global__ void rnn_norm_kernel(const float* __restrict__ init,     // [N,128]
                                const float* __restrict__ patient,  // [P,128]
                                const float* __restrict__ td,       // [B,1]
                                const float* __restrict__ feat,     // [B,128]
                                const float* __restrict__ Wih,      // [128,257]
                                const float* __restrict__ bih,      // [128]
                                const float* __restrict__ Whh,      // [128,128]
                                const float* __restrict__ bhh,      // [128]
                                const int* __restrict__ codeid,     // [B]
                                const int* __restrict__ patientid,  // [1]
                                float* __restrict__ out) {          // [B,128]
    __shared__ float s_in[IN_RNN];
    __shared__ float s_ce[D];
    __shared__ float s_red[D];

    const int b = blockIdx.x;
    const int d = threadIdx.x;       // 0..127
    const int pid = patientid[0];

    s_in[d] = patient[pid * 128 + d];
    if (d == 0) s_in[128] = td[b];
    s_in[129 + d] = feat[b * 128 + d];

    // Layer-2 aggregation + blend + ReLU for this row only (fp32 accum)
    const int cid = codeid[b];
    {
        int s = g_start[cid];
        int e = g_start[cid + 1];
        float a = 0.f;
        for (int i = s; i < e; i++) {
            int2 m = g_edge2[i];     // uniform across block -> broadcast
            a = fmaf(__int_as_float(m.y),
                     __half2float(g_support[(long)m.x * 128 + d]), a);
        }
        float ini = init[(long)cid * 128 + d];
        s_ce[d] = fmaxf(ALPHA * a + (1.f - ALPHA) * ini, 0.f);
    }
    __syncthreads();

    float acc = bih[d] + bhh[d];
    const float* wih = &Wih[d * IN_RNN];
    #pragma unroll 4
    for (int k = 0; k < IN_RNN; k++) acc = fmaf(s_in[k], wih[k], acc);
    const float* whh = &Whh[d * D];
    #pragma unroll 4
    for (int k = 0; k < D; k++) acc = fmaf(s_ce[k], whh[k], acc);

    float h = tanhf(acc);
    s_red[d] = h * h;
    __syncthreads();
    #pragma unroll
    for (int s = 64; s > 0; s >>= 1) {
        if (d < s) s_red[d] += s_red[d + s];
        __syncthreads();
    }
    float nrm = fmaxf(sqrtf(s_red[0]), 1e-12f);
    out[b * 128 + d] = h / nrm;
}

// ---------------------------------------------------------------------------
extern "C" void kernel_launch(void* const* d_in, const int* in_sizes, int n_in,
                              void* d_out, int out_size) {
    const float* code_dynamic = (const float*)d_in[0];
    const float* init_x       = (const float*)d_in[1];
    const float* patient      = (const float*)d_in[2];
    const float* timediffs    = (const float*)d_in[3];
    const float* features     = (const float*)d_in[4];
    const float* edge_val     = (const float*)d_in[5];
    const float* W1           = (const float*)d_in[6];
    const float* W2           = (const float*)d_in[7];
    const float* W_ih         = (const float*)d_in[8];
    const float* b_ih         = (const float*)d_in[9];
    const float* W_hh         = (const float*)d_in[10];
    const float* b_hh         = (const float*)d_in[11];
    const int*   edge_row     = (const int*)d_in[12];
    const int*   edge_col     = (const int*)d_in[13];
    const int*   codeid       = (const int*)d_in[14];
    const int*   patientid    = (const int*)d_in[15];
    float* out = (float*)d_out;

    const int n_nodes = in_sizes[0] / D;         // 60000
    const int n_edges = in_sizes[5];             // 600000
    const int batch   = in_sizes[14];            // 256

    const int gemm_grid = (n_nodes + 31) / 32;
    const int node_grid = (n_nodes + 255) / 256;
    const int edge_grid = (n_edges + 255) / 256;
    const int pull_grid = (n_nodes * 32 + 255) / 256;

    // W -> fp16 (once per launch)
    convert_w_kernel<<<(D * D + 255) / 256, 256>>>(W1, W2);

    // CSR build (once per launch; edges shared by both layers)
    csr_zero_kernel<<<node_grid, 256>>>(n_nodes);
    csr_hist_kernel<<<edge_grid, 256>>>(edge_row, n_edges);
    csr_scan_kernel<<<1, SCAN_THREADS>>>(n_nodes);
    csr_fill_kernel<<<edge_grid, 256>>>(edge_row, edge_col, edge_val, n_edges);

    // Layer 1
    gemm_half<1><<<gemm_grid, 256>>>(code_dynamic, n_nodes);
    pull_kernel<<<pull_grid, 256>>>(init_x, n_nodes);

    // Layer 2 (GEMM only; aggregation for the 256 needed rows happens in rnn)
    gemm_half<2><<<gemm_grid, 256>>>(nullptr, n_nodes);

    // Fused layer-2 pull (256 rows) + RNN + normalize
    rnn_norm_kernel<<<batch, 128>>>(init_x, patient, timediffs, features,
                                    W_ih, b_ih, W_hh, b_hh, codeid, patientid, out);
}